// round 4
// baseline (speedup 1.0000x reference)
#include <cuda_runtime.h>
#include <cuda_bf16.h>

// QuantumFeatureExtractor — closed-form, float4-vectorized, 4 patches/thread.
//
//   m0 = cos(t4)cos(t0)cos(a0) - sin(t4)cos(t2)sin(a0)sin(a2)
//   m1 = cos(a1 + t1)
//   m2 = cos(t0)cos(a0)cos(a2)
//   m3 = cos(a1 + t1) * cos(t3) * cos(a3)
//
// Work unit = one float4-column pair of a patch row (2 patches).
// 262144 units total; each thread does units k and k+131072 (same i,j4,
// batch b and b+64), so all 4 LDG.128 are issued back-to-back up front.

__device__ __forceinline__ float4 qfe_patch(float a0, float a1, float a2, float a3,
                                            float A, float Bc, float ct0, float ct3,
                                            float t1) {
    float s0, c0, s2, c2;
    __sincosf(a0, &s0, &c0);
    __sincosf(a2, &s2, &c2);
    const float m1 = __cosf(a1 + t1);
    const float c3 = __cosf(a3);
    const float m0 = fmaf(A, c0, -Bc * (s0 * s2));
    const float m2 = ct0 * (c0 * c2);
    const float m3 = m1 * (ct3 * c3);
    return make_float4(m0, m1, m2, m3);
}

__global__ void __launch_bounds__(128) qfe_main(const float4* __restrict__ x4,
                                                const float* __restrict__ tp,
                                                float4* __restrict__ out4) {
    const int k  = blockIdx.x * 128 + threadIdx.x;   // 131072 threads
    const int j4 = k & 31;          // float4 column (covers patches 2j4, 2j4+1)
    const int i  = (k >> 5) & 63;   // patch row
    const int b  = k >> 11;         // batch 0..63 (unit 2 adds +64)

    // Input float4 index: image = 4096 float4; row 2i -> i*64, row 2i+1 -> +32.
    const int in1 = b * 4096 + i * 64 + j4;
    const int in2 = in1 + 262144;   // batch b+64, same (i, j4)

    // Batch all 4 global loads up front (MLP_p1 = 4).
    const float4 rA1 = x4[in1];
    const float4 rB1 = x4[in1 + 32];
    const float4 rA2 = x4[in2];
    const float4 rB2 = x4[in2 + 32];

    // Uniform circuit params — computed while the loads are in flight.
    const float t0 = tp[0], t1 = tp[1], t2 = tp[2], t3 = tp[3], t4 = tp[4];
    float st4, ct4;
    __sincosf(t4, &st4, &ct4);
    const float ct0 = __cosf(t0);
    const float ct2 = __cosf(t2);
    const float ct3 = __cosf(t3);
    const float A  = ct4 * ct0;
    const float Bc = st4 * ct2;

    // Unit 1: patches (b, i, 2j4) and (b, i, 2j4+1)
    const float4 o1a = qfe_patch(rA1.x, rA1.y, rB1.x, rB1.y, A, Bc, ct0, ct3, t1);
    const float4 o1b = qfe_patch(rA1.z, rA1.w, rB1.z, rB1.w, A, Bc, ct0, ct3, t1);
    // Unit 2: same for batch b+64
    const float4 o2a = qfe_patch(rA2.x, rA2.y, rB2.x, rB2.y, A, Bc, ct0, ct3, t1);
    const float4 o2b = qfe_patch(rA2.z, rA2.w, rB2.z, rB2.w, A, Bc, ct0, ct3, t1);

    // Output float4 index = b*4096 + i*64 + patch; lane t writes 2t, 2t+1
    // -> warp covers a contiguous 64-float4 span. Fully coalesced.
    const int on1 = b * 4096 + i * 64 + 2 * j4;
    const int on2 = on1 + 262144;
    out4[on1]     = o1a;
    out4[on1 + 1] = o1b;
    out4[on2]     = o2a;
    out4[on2 + 1] = o2b;
}

extern "C" void kernel_launch(void* const* d_in, const int* in_sizes, int n_in,
                              void* d_out, int out_size) {
    const float* x  = (const float*)d_in[0];
    const float* tp = (const float*)d_in[1];
    if (n_in >= 2 && in_sizes[0] == 6) {   // defensive vs metadata ordering
        const float* s = x; x = tp; tp = s;
    }
    qfe_main<<<1024, 128>>>((const float4*)x, tp, (float4*)d_out);
}